// round 4
// baseline (speedup 1.0000x reference)
#include <cuda_runtime.h>
#include <cuda_fp16.h>
#include <math.h>

#define Hh 240
#define Ww 240
#define NPIX 57600           // 240*240
#define BMAX 256

// ---------------- scratch (no cudaMalloc allowed) ----------------
__device__ __half2 g_s1h[BMAX * NPIX];  // after K1: [b][kw][h]  (re,im) fp16
__device__ __half2 g_s2h[BMAX * NPIX];  // after K2: [b][h][kw]  (re,im) fp16
__device__ float2 g_tw[240];            // forward twiddles e^{-2*pi*i*j/240}

// smem: SoA, row v at offset 240*v + 2*(v>>1)  (rows of a warp-pair are
// contiguous 480 floats; bank bases conflict-free for all access patterns)
#define SMF (16*240 + 16)

// ---------------- complex helpers ----------------
__device__ __forceinline__ float2 cadd(float2 a, float2 b){ return make_float2(a.x+b.x, a.y+b.y); }
__device__ __forceinline__ float2 csub(float2 a, float2 b){ return make_float2(a.x-b.x, a.y-b.y); }
__device__ __forceinline__ float2 cmul(float2 a, float2 b){
    return make_float2(a.x*b.x - a.y*b.y, a.x*b.y + a.y*b.x);
}

// DIR = -1 forward (e^{-i}), +1 inverse (e^{+i})
template<int DIR>
__device__ __forceinline__ void dft4(float2 a[4]) {
    float2 u0 = cadd(a[0], a[2]);
    float2 u1 = csub(a[0], a[2]);
    float2 u2 = cadd(a[1], a[3]);
    float2 u3 = csub(a[1], a[3]);
    float2 j3 = make_float2((DIR < 0) ? u3.y : -u3.y, (DIR < 0) ? -u3.x : u3.x);
    a[0] = cadd(u0, u2);
    a[2] = csub(u0, u2);
    a[1] = cadd(u1, j3);
    a[3] = csub(u1, j3);
}

__device__ __constant__ float C16c[10] = {1.f,0.92387953f,0.70710678f,0.38268343f,0.f,-0.38268343f,-0.70710678f,-0.92387953f,-1.f,-0.92387953f};
__device__ __constant__ float S16c[10] = {0.f,0.38268343f,0.70710678f,0.92387953f,1.f,0.92387953f,0.70710678f,0.38268343f,0.f,-0.38268343f};
__device__ __constant__ float C15c[9] = {1.f,0.91354546f,0.66913061f,0.30901699f,-0.10452846f,-0.5f,-0.80901699f,-0.97814760f,-0.97814760f};
__device__ __constant__ float S15c[9] = {0.f,0.40673664f,0.74314483f,0.95105652f,0.99452190f,0.86602540f,0.58778525f,0.20791169f,-0.20791169f};

template<int DIR>
__device__ __forceinline__ void fft16(float2 a[16]) {
    float2 b[4][4];
#pragma unroll
    for (int n2 = 0; n2 < 4; n2++) {
        float2 t[4];
#pragma unroll
        for (int n1 = 0; n1 < 4; n1++) t[n1] = a[4*n1 + n2];
        dft4<DIR>(t);
#pragma unroll
        for (int k1 = 0; k1 < 4; k1++) {
            const int j = n2 * k1;
            float2 w = make_float2(C16c[j], (DIR < 0) ? -S16c[j] : S16c[j]);
            b[n2][k1] = cmul(t[k1], w);
        }
    }
#pragma unroll
    for (int k1 = 0; k1 < 4; k1++) {
        float2 t[4];
#pragma unroll
        for (int n2 = 0; n2 < 4; n2++) t[n2] = b[n2][k1];
        dft4<DIR>(t);
#pragma unroll
        for (int k2 = 0; k2 < 4; k2++) a[k1 + 4*k2] = t[k2];
    }
}

template<int DIR>
__device__ __forceinline__ void dft5(float2 a[5]) {
    const float c1 = 0.309016994f, s1 = 0.951056516f;
    const float c2 = -0.809016994f, s2 = 0.587785252f;
    float2 a0 = a[0];
    float2 t1 = cadd(a[1], a[4]);
    float2 t2 = cadd(a[2], a[3]);
    float2 t3 = csub(a[1], a[4]);
    float2 t4 = csub(a[2], a[3]);
    float2 m1 = make_float2(a0.x + c1*t1.x + c2*t2.x, a0.y + c1*t1.y + c2*t2.y);
    float2 m2 = make_float2(a0.x + c2*t1.x + c1*t2.x, a0.y + c2*t1.y + c1*t2.y);
    float2 p1 = make_float2(s1*t3.x + s2*t4.x, s1*t3.y + s2*t4.y);
    float2 p2 = make_float2(s2*t3.x - s1*t4.x, s2*t3.y - s1*t4.y);
    float2 j1 = make_float2((DIR < 0) ? p1.y : -p1.y, (DIR < 0) ? -p1.x : p1.x);
    float2 j2 = make_float2((DIR < 0) ? p2.y : -p2.y, (DIR < 0) ? -p2.x : p2.x);
    a[0] = make_float2(a0.x + t1.x + t2.x, a0.y + t1.y + t2.y);
    a[1] = cadd(m1, j1);
    a[4] = csub(m1, j1);
    a[2] = cadd(m2, j2);
    a[3] = csub(m2, j2);
}

template<int DIR>
__device__ __forceinline__ void dft3(float2 a[3]) {
    const float s3 = 0.866025404f;
    float2 a0 = a[0];
    float2 t1 = cadd(a[1], a[2]);
    float2 t2 = csub(a[1], a[2]);
    float2 m = make_float2(a0.x - 0.5f*t1.x, a0.y - 0.5f*t1.y);
    float2 jt = make_float2((DIR < 0) ? s3*t2.y : -s3*t2.y, (DIR < 0) ? -s3*t2.x : s3*t2.x);
    a[0] = make_float2(a0.x + t1.x, a0.y + t1.y);
    a[1] = cadd(m, jt);
    a[2] = csub(m, jt);
}

template<int DIR>
__device__ __forceinline__ void fft15(float2 a[15]) {
    float2 c[3][5];
#pragma unroll
    for (int m2 = 0; m2 < 3; m2++) {
        float2 t[5];
#pragma unroll
        for (int m1 = 0; m1 < 5; m1++) t[m1] = a[3*m1 + m2];
        dft5<DIR>(t);
#pragma unroll
        for (int p1 = 0; p1 < 5; p1++) {
            const int j = m2 * p1;
            float2 w = make_float2(C15c[j], (DIR < 0) ? -S15c[j] : S15c[j]);
            c[m2][p1] = cmul(t[p1], w);
        }
    }
#pragma unroll
    for (int p1 = 0; p1 < 5; p1++) {
        float2 t[3] = {c[0][p1], c[1][p1], c[2][p1]};
        dft3<DIR>(t);
        a[p1]      = t[0];
        a[p1 + 5]  = t[1];
        a[p1 + 10] = t[2];
    }
}

// ---- stage pieces (warp-private rows; only __syncwarp) ----

// stage 1, inputs already in smem (complex)
template<int DIR>
__device__ __forceinline__ void stage1_s(float* re, float* im, int t) {
    if (t < 15) {
        float2 a[16];
#pragma unroll
        for (int n1 = 0; n1 < 16; n1++) { a[n1].x = re[15*n1 + t]; a[n1].y = im[15*n1 + t]; }
        fft16<DIR>(a);
#pragma unroll
        for (int k1 = 1; k1 < 16; k1++) {
            float2 w = __ldg(&g_tw[t * k1]);
            if (DIR > 0) w.y = -w.y;
            a[k1] = cmul(a[k1], w);
        }
#pragma unroll
        for (int k1 = 0; k1 < 16; k1++) { re[15*k1 + t] = a[k1].x; im[15*k1 + t] = a[k1].y; }
    }
    __syncwarp();
}

// stage 1, real inputs loaded directly from global (imag literal 0 -> folded flops)
__device__ __forceinline__ void stage1_g_real(const float* __restrict__ gsrc,
                                              float* re, float* im, int t) {
    if (t < 15) {
        float2 a[16];
#pragma unroll
        for (int n1 = 0; n1 < 16; n1++) a[n1] = make_float2(__ldg(&gsrc[15*n1 + t]), 0.0f);
        fft16<-1>(a);
#pragma unroll
        for (int k1 = 1; k1 < 16; k1++) {
            float2 w = __ldg(&g_tw[t * k1]);
            a[k1] = cmul(a[k1], w);
        }
#pragma unroll
        for (int k1 = 0; k1 < 16; k1++) { re[15*k1 + t] = a[k1].x; im[15*k1 + t] = a[k1].y; }
    }
    __syncwarp();
}

// stage 2, complex out in smem (natural order)
template<int DIR>
__device__ __forceinline__ void stage2(float* re, float* im, int t) {
    float2 b[15];
#pragma unroll
    for (int n2 = 0; n2 < 15; n2++) { b[n2].x = re[15*t + n2]; b[n2].y = im[15*t + n2]; }
    fft15<DIR>(b);
    __syncwarp();
    const float sc = (DIR > 0) ? (1.0f / 240.0f) : 1.0f;
#pragma unroll
    for (int j = 0; j < 15; j++) { re[t + 16*j] = b[j].x * sc; im[t + 16*j] = b[j].y * sc; }
    __syncwarp();
}

// stage 2 inverse + magnitude: writes |z|/240 into re[] only
__device__ __forceinline__ void stage2_mag(float* re, float* im, int t) {
    float2 b[15];
#pragma unroll
    for (int n2 = 0; n2 < 15; n2++) { b[n2].x = re[15*t + n2]; b[n2].y = im[15*t + n2]; }
    fft15<1>(b);
    __syncwarp();
    const float sc = 1.0f / 240.0f;
#pragma unroll
    for (int j = 0; j < 15; j++)
        re[t + 16*j] = sc * sqrtf(b[j].x * b[j].x + b[j].y * b[j].y);
    __syncwarp();
}

// ---------------- kernels ----------------
__global__ void init_tw_kernel() {
    int j = threadIdx.x;
    if (j < 240) {
        float s, c;
        sincosf(-6.283185307179586f * (float)j / 240.0f, &s, &c);
        g_tw[j] = make_float2(c, s);
    }
}

__device__ __forceinline__ int rowoff(int v) { return 240 * v + 2 * (v >> 1); }

// K1: forward row FFTs of real input x[b][h][w] -> g_s1h[b][kw][h]
__global__ __launch_bounds__(256) void k_rowfft(const float* __restrict__ x) {
    __shared__ float sre[SMF], sim[SMF];
    const int b = blockIdx.y;
    const int h0 = blockIdx.x * 16;
    const int tid = threadIdx.x;
    const int w = tid >> 5, lane = tid & 31;
    const int t = lane & 15, h = lane >> 4;

    // stage 1 directly from global (real input), warp w owns rows 2w,2w+1
    const float* gsrc = x + ((size_t)b * 240 + h0 + 2 * w + h) * 240;
    float* re = sre + 482 * w + 240 * h;
    float* im = sim + 482 * w + 240 * h;
    stage1_g_real(gsrc, re, im, t);
    stage2<-1>(re, im, t);
    __syncthreads();

    // block-wide transposed fp16 store (coalesced 64B segments)
    const int r = tid & 15;
    const int kwb = tid >> 4;
    const float* bre = sre + rowoff(r);
    const float* bim = sim + rowoff(r);
    __half2* dst = g_s1h + (size_t)b * NPIX + h0 + r;
#pragma unroll
    for (int j = 0; j < 15; j++) {
        int kw = kwb + 16 * j;
        dst[(size_t)kw * 240] = __floats2half2_rn(bre[kw], bim[kw]);
    }
}

// K2: column FFT + data-consistency combine + column IFFT
__global__ __launch_bounds__(256) void k_colfft(const float* __restrict__ yk,
                                                const float* __restrict__ Am) {
    __shared__ float sre[SMF], sim[SMF];
    const int b = blockIdx.y;
    const int kw0 = blockIdx.x * 16;
    const int tid = threadIdx.x;
    const int w = tid >> 5, lane = tid & 31;
    const int t = lane & 15, h = lane >> 4;

    // warp-private load: cols kw0+2w, kw0+2w+1 (contiguous 480 half2)
    const __half2* sp = g_s1h + ((size_t)b * 240 + kw0 + 2 * w) * 240;
    float* wre = sre + 482 * w;
    float* wim = sim + 482 * w;
#pragma unroll
    for (int j = 0; j < 15; j++) {
        int idx = lane + 32 * j;
        float2 v = __half22float2(sp[idx]);
        wre[idx] = v.x;
        wim[idx] = v.y;
    }
    __syncwarp();

    float* re = wre + 240 * h;
    float* im = wim + 240 * h;
    stage1_s<-1>(re, im, t);
    stage2<-1>(re, im, t);
    __syncthreads();

    // combine: z_k = (1-A)*x2_k + y_k   (block-wide, global-coalesced)
    const float* yr = yk + (size_t)b * (2 * NPIX);
    const float* yi = yr + NPIX;
    {
        const int v = tid & 15;
        const int khb = tid >> 4;
        float* cre = sre + rowoff(v);
        float* cim = sim + rowoff(v);
#pragma unroll
        for (int j = 0; j < 15; j++) {
            int kh = khb + 16 * j;
            int idx = kh * 240 + kw0 + v;
            float a = 1.0f - __ldg(&Am[idx]);
            cre[kh] = cre[kh] * a + __ldg(&yr[idx]);
            cim[kh] = cim[kh] * a + __ldg(&yi[idx]);
        }
    }
    __syncthreads();

    stage1_s<1>(re, im, t);
    stage2<1>(re, im, t);
    __syncthreads();

    // block-wide transposed fp16 store
    {
        const int v = tid & 15;
        const int hb = tid >> 4;
        const float* cre = sre + rowoff(v);
        const float* cim = sim + rowoff(v);
        __half2* dst = g_s2h + (size_t)b * NPIX + kw0 + v;
#pragma unroll
        for (int j = 0; j < 15; j++) {
            int hh = hb + 16 * j;
            dst[(size_t)hh * 240] = __floats2half2_rn(cre[hh], cim[hh]);
        }
    }
}

// K3: inverse row FFTs + abs -> out[b][h][w]  (fully warp-private, no block sync)
__global__ __launch_bounds__(256) void k_invrow(float* __restrict__ out) {
    __shared__ float sre[SMF], sim[SMF];
    const int b = blockIdx.y;
    const int h0 = blockIdx.x * 16;
    const int tid = threadIdx.x;
    const int w = tid >> 5, lane = tid & 31;
    const int t = lane & 15, h = lane >> 4;

    const __half2* sp = g_s2h + ((size_t)b * 240 + h0 + 2 * w) * 240;
    float* wre = sre + 482 * w;
    float* wim = sim + 482 * w;
#pragma unroll
    for (int j = 0; j < 15; j++) {
        int idx = lane + 32 * j;
        float2 v = __half22float2(sp[idx]);
        wre[idx] = v.x;
        wim[idx] = v.y;
    }
    __syncwarp();

    float* re = wre + 240 * h;
    float* im = wim + 240 * h;
    stage1_s<1>(re, im, t);
    stage2_mag(re, im, t);   // magnitudes land in wre[0..479]

    float* ob = out + ((size_t)b * 240 + h0 + 2 * w) * 240;
#pragma unroll
    for (int j = 0; j < 15; j++) {
        int idx = lane + 32 * j;
        ob[idx] = wre[idx];
    }
}

extern "C" void kernel_launch(void* const* d_in, const int* in_sizes, int n_in,
                              void* d_out, int out_size) {
    const float* T2_Gen    = (const float*)d_in[0];  // [B,1,240,240] f32
    const float* underT2_K = (const float*)d_in[1];  // [B,2,240,240] f32
    const float* A         = (const float*)d_in[2];  // [240,240] f32
    float* out = (float*)d_out;

    int B = in_sizes[0] / NPIX;   // 256
    dim3 grid(15, B);

    init_tw_kernel<<<1, 256>>>();
    k_rowfft<<<grid, 256>>>(T2_Gen);
    k_colfft<<<grid, 256>>>(underT2_K, A);
    k_invrow<<<grid, 256>>>(out);
}

// round 5
// speedup vs baseline: 1.4379x; 1.4379x over previous
#include <cuda_runtime.h>
#include <math.h>

#define Hh 240
#define Ww 240
#define NPIX 57600           // 240*240
#define BMAX 256

// ---------------- scratch (no cudaMalloc allowed) ----------------
__device__ float2 g_s1[BMAX * NPIX];   // after K1: [b][kw][h]
__device__ float2 g_s2[BMAX * NPIX];   // after K2: [b][h][kw]
__device__ float2 g_tw[240];           // forward twiddles e^{-2*pi*i*j/240}

// smem: SoA, row v at offset 240*v + 2*(v>>1) (conflict-free; see R3 analysis)
#define SMF (16*240 + 16)

// ---------------- complex helpers ----------------
__device__ __forceinline__ float2 cadd(float2 a, float2 b){ return make_float2(a.x+b.x, a.y+b.y); }
__device__ __forceinline__ float2 csub(float2 a, float2 b){ return make_float2(a.x-b.x, a.y-b.y); }
__device__ __forceinline__ float2 cmul(float2 a, float2 b){
    return make_float2(a.x*b.x - a.y*b.y, a.x*b.y + a.y*b.x);
}

// DIR = -1 forward (e^{-i}), +1 inverse (e^{+i})
template<int DIR>
__device__ __forceinline__ void dft4(float2 a[4]) {
    float2 u0 = cadd(a[0], a[2]);
    float2 u1 = csub(a[0], a[2]);
    float2 u2 = cadd(a[1], a[3]);
    float2 u3 = csub(a[1], a[3]);
    float2 j3 = make_float2((DIR < 0) ? u3.y : -u3.y, (DIR < 0) ? -u3.x : u3.x);
    a[0] = cadd(u0, u2);
    a[2] = csub(u0, u2);
    a[1] = cadd(u1, j3);
    a[3] = csub(u1, j3);
}

__device__ __constant__ float C16c[10] = {1.f,0.92387953f,0.70710678f,0.38268343f,0.f,-0.38268343f,-0.70710678f,-0.92387953f,-1.f,-0.92387953f};
__device__ __constant__ float S16c[10] = {0.f,0.38268343f,0.70710678f,0.92387953f,1.f,0.92387953f,0.70710678f,0.38268343f,0.f,-0.38268343f};
__device__ __constant__ float C15c[9] = {1.f,0.91354546f,0.66913061f,0.30901699f,-0.10452846f,-0.5f,-0.80901699f,-0.97814760f,-0.97814760f};
__device__ __constant__ float S15c[9] = {0.f,0.40673664f,0.74314483f,0.95105652f,0.99452190f,0.86602540f,0.58778525f,0.20791169f,-0.20791169f};

template<int DIR>
__device__ __forceinline__ void fft16(float2 a[16]) {
    float2 b[4][4];
#pragma unroll
    for (int n2 = 0; n2 < 4; n2++) {
        float2 t[4];
#pragma unroll
        for (int n1 = 0; n1 < 4; n1++) t[n1] = a[4*n1 + n2];
        dft4<DIR>(t);
#pragma unroll
        for (int k1 = 0; k1 < 4; k1++) {
            const int j = n2 * k1;
            float2 w = make_float2(C16c[j], (DIR < 0) ? -S16c[j] : S16c[j]);
            b[n2][k1] = cmul(t[k1], w);
        }
    }
#pragma unroll
    for (int k1 = 0; k1 < 4; k1++) {
        float2 t[4];
#pragma unroll
        for (int n2 = 0; n2 < 4; n2++) t[n2] = b[n2][k1];
        dft4<DIR>(t);
#pragma unroll
        for (int k2 = 0; k2 < 4; k2++) a[k1 + 4*k2] = t[k2];
    }
}

template<int DIR>
__device__ __forceinline__ void dft5(float2 a[5]) {
    const float c1 = 0.309016994f, s1 = 0.951056516f;
    const float c2 = -0.809016994f, s2 = 0.587785252f;
    float2 a0 = a[0];
    float2 t1 = cadd(a[1], a[4]);
    float2 t2 = cadd(a[2], a[3]);
    float2 t3 = csub(a[1], a[4]);
    float2 t4 = csub(a[2], a[3]);
    float2 m1 = make_float2(a0.x + c1*t1.x + c2*t2.x, a0.y + c1*t1.y + c2*t2.y);
    float2 m2 = make_float2(a0.x + c2*t1.x + c1*t2.x, a0.y + c2*t1.y + c1*t2.y);
    float2 p1 = make_float2(s1*t3.x + s2*t4.x, s1*t3.y + s2*t4.y);
    float2 p2 = make_float2(s2*t3.x - s1*t4.x, s2*t3.y - s1*t4.y);
    float2 j1 = make_float2((DIR < 0) ? p1.y : -p1.y, (DIR < 0) ? -p1.x : p1.x);
    float2 j2 = make_float2((DIR < 0) ? p2.y : -p2.y, (DIR < 0) ? -p2.x : p2.x);
    a[0] = make_float2(a0.x + t1.x + t2.x, a0.y + t1.y + t2.y);
    a[1] = cadd(m1, j1);
    a[4] = csub(m1, j1);
    a[2] = cadd(m2, j2);
    a[3] = csub(m2, j2);
}

template<int DIR>
__device__ __forceinline__ void dft3(float2 a[3]) {
    const float s3 = 0.866025404f;
    float2 a0 = a[0];
    float2 t1 = cadd(a[1], a[2]);
    float2 t2 = csub(a[1], a[2]);
    float2 m = make_float2(a0.x - 0.5f*t1.x, a0.y - 0.5f*t1.y);
    float2 jt = make_float2((DIR < 0) ? s3*t2.y : -s3*t2.y, (DIR < 0) ? -s3*t2.x : s3*t2.x);
    a[0] = make_float2(a0.x + t1.x, a0.y + t1.y);
    a[1] = cadd(m, jt);
    a[2] = csub(m, jt);
}

template<int DIR>
__device__ __forceinline__ void fft15(float2 a[15]) {
    float2 c[3][5];
#pragma unroll
    for (int m2 = 0; m2 < 3; m2++) {
        float2 t[5];
#pragma unroll
        for (int m1 = 0; m1 < 5; m1++) t[m1] = a[3*m1 + m2];
        dft5<DIR>(t);
#pragma unroll
        for (int p1 = 0; p1 < 5; p1++) {
            const int j = m2 * p1;
            float2 w = make_float2(C15c[j], (DIR < 0) ? -S15c[j] : S15c[j]);
            c[m2][p1] = cmul(t[p1], w);
        }
    }
#pragma unroll
    for (int p1 = 0; p1 < 5; p1++) {
        float2 t[3] = {c[0][p1], c[1][p1], c[2][p1]};
        dft3<DIR>(t);
        a[p1]      = t[0];
        a[p1 + 5]  = t[1];
        a[p1 + 10] = t[2];
    }
}

// ---- stage pieces (warp-private rows; only __syncwarp) ----

// common tail of stage1: twiddle + write smem
template<int DIR>
__device__ __forceinline__ void stage1_tail(float2 a[16], float* re, float* im, int t) {
#pragma unroll
    for (int k1 = 1; k1 < 16; k1++) {
        float2 w = __ldg(&g_tw[t * k1]);
        if (DIR > 0) w.y = -w.y;
        a[k1] = cmul(a[k1], w);
    }
#pragma unroll
    for (int k1 = 0; k1 < 16; k1++) { re[15*k1 + t] = a[k1].x; im[15*k1 + t] = a[k1].y; }
}

// stage 1, inputs already in smem (complex)
template<int DIR>
__device__ __forceinline__ void stage1_s(float* re, float* im, int t) {
    if (t < 15) {
        float2 a[16];
#pragma unroll
        for (int n1 = 0; n1 < 16; n1++) { a[n1].x = re[15*n1 + t]; a[n1].y = im[15*n1 + t]; }
        fft16<DIR>(a);
        stage1_tail<DIR>(a, re, im, t);
    }
    __syncwarp();
}

// stage 1, complex inputs loaded directly from global (contiguous float2 row)
template<int DIR>
__device__ __forceinline__ void stage1_g(const float2* __restrict__ gsrc,
                                         float* re, float* im, int t) {
    if (t < 15) {
        float2 a[16];
#pragma unroll
        for (int n1 = 0; n1 < 16; n1++) a[n1] = __ldg(&gsrc[15*n1 + t]);
        fft16<DIR>(a);
        stage1_tail<DIR>(a, re, im, t);
    }
    __syncwarp();
}

// stage 1, real inputs loaded directly from global (imag literal 0 -> folded flops)
__device__ __forceinline__ void stage1_g_real(const float* __restrict__ gsrc,
                                              float* re, float* im, int t) {
    if (t < 15) {
        float2 a[16];
#pragma unroll
        for (int n1 = 0; n1 < 16; n1++) a[n1] = make_float2(__ldg(&gsrc[15*n1 + t]), 0.0f);
        fft16<-1>(a);
        stage1_tail<-1>(a, re, im, t);
    }
    __syncwarp();
}

// stage 2, complex out in smem (natural order)
template<int DIR>
__device__ __forceinline__ void stage2(float* re, float* im, int t) {
    float2 b[15];
#pragma unroll
    for (int n2 = 0; n2 < 15; n2++) { b[n2].x = re[15*t + n2]; b[n2].y = im[15*t + n2]; }
    fft15<DIR>(b);
    __syncwarp();
    const float sc = (DIR > 0) ? (1.0f / 240.0f) : 1.0f;
#pragma unroll
    for (int j = 0; j < 15; j++) { re[t + 16*j] = b[j].x * sc; im[t + 16*j] = b[j].y * sc; }
    __syncwarp();
}

// stage 2 inverse + magnitude, stored DIRECTLY to global (row-contiguous dst):
// lane t owns outputs k = t+16j -> per j each half-warp writes 64B contiguous.
__device__ __forceinline__ void stage2_mag_g(const float* re, const float* im, int t,
                                             float* __restrict__ gdst) {
    float2 b[15];
#pragma unroll
    for (int n2 = 0; n2 < 15; n2++) { b[n2].x = re[15*t + n2]; b[n2].y = im[15*t + n2]; }
    fft15<1>(b);
    const float sc = 1.0f / 240.0f;
#pragma unroll
    for (int j = 0; j < 15; j++)
        gdst[t + 16*j] = sc * sqrtf(b[j].x * b[j].x + b[j].y * b[j].y);
}

// ---------------- kernels ----------------
__global__ void init_tw_kernel() {
    int j = threadIdx.x;
    if (j < 240) {
        float s, c;
        sincosf(-6.283185307179586f * (float)j / 240.0f, &s, &c);
        g_tw[j] = make_float2(c, s);
    }
}

__device__ __forceinline__ int rowoff(int v) { return 240 * v + 2 * (v >> 1); }

// K1: forward row FFTs of real input x[b][h][w] -> g_s1[b][kw][h]
__global__ __launch_bounds__(256) void k_rowfft(const float* __restrict__ x) {
    __shared__ float sre[SMF], sim[SMF];
    const int b = blockIdx.y;
    const int h0 = blockIdx.x * 16;
    const int tid = threadIdx.x;
    const int w = tid >> 5, lane = tid & 31;
    const int t = lane & 15, h = lane >> 4;

    // stage 1 directly from global (real input), warp w owns rows 2w,2w+1
    const float* gsrc = x + ((size_t)b * 240 + h0 + 2 * w + h) * 240;
    float* re = sre + 482 * w + 240 * h;
    float* im = sim + 482 * w + 240 * h;
    stage1_g_real(gsrc, re, im, t);
    stage2<-1>(re, im, t);
    __syncthreads();

    // block-wide transposed store (coalesced: 16 consecutive h per kw)
    const int r = tid & 15;
    const int kwb = tid >> 4;
    const float* bre = sre + rowoff(r);
    const float* bim = sim + rowoff(r);
    float2* dst = g_s1 + (size_t)b * NPIX + h0 + r;
#pragma unroll
    for (int j = 0; j < 15; j++) {
        int kw = kwb + 16 * j;
        dst[(size_t)kw * 240] = make_float2(bre[kw], bim[kw]);
    }
}

// K2: column FFT + data-consistency combine + column IFFT
__global__ __launch_bounds__(256) void k_colfft(const float* __restrict__ yk,
                                                const float* __restrict__ Am) {
    __shared__ float sre[SMF], sim[SMF];
    const int b = blockIdx.y;
    const int kw0 = blockIdx.x * 16;
    const int tid = threadIdx.x;
    const int w = tid >> 5, lane = tid & 31;
    const int t = lane & 15, h = lane >> 4;

    float* re = sre + 482 * w + 240 * h;
    float* im = sim + 482 * w + 240 * h;

    // forward column FFT: stage 1 loads its comb directly from g_s1 row
    const float2* gsrc = g_s1 + ((size_t)b * 240 + kw0 + 2 * w + h) * 240;
    stage1_g<-1>(gsrc, re, im, t);
    stage2<-1>(re, im, t);
    __syncthreads();

    // combine: z_k = (1-A)*x2_k + y_k   (block-wide, global-coalesced)
    const float* yr = yk + (size_t)b * (2 * NPIX);
    const float* yi = yr + NPIX;
    {
        const int v = tid & 15;
        const int khb = tid >> 4;
        float* cre = sre + rowoff(v);
        float* cim = sim + rowoff(v);
#pragma unroll
        for (int j = 0; j < 15; j++) {
            int kh = khb + 16 * j;
            int idx = kh * 240 + kw0 + v;
            float a = 1.0f - __ldg(&Am[idx]);
            cre[kh] = cre[kh] * a + __ldg(&yr[idx]);
            cim[kh] = cim[kh] * a + __ldg(&yi[idx]);
        }
    }
    __syncthreads();

    stage1_s<1>(re, im, t);
    stage2<1>(re, im, t);
    __syncthreads();

    // block-wide transposed store (coalesced: 16 consecutive kw per h)
    {
        const int v = tid & 15;
        const int hb = tid >> 4;
        const float* cre = sre + rowoff(v);
        const float* cim = sim + rowoff(v);
        float2* dst = g_s2 + (size_t)b * NPIX + kw0 + v;
#pragma unroll
        for (int j = 0; j < 15; j++) {
            int hh = hb + 16 * j;
            dst[(size_t)hh * 240] = make_float2(cre[hh], cim[hh]);
        }
    }
}

// K3: inverse row FFTs + abs -> out[b][h][w]
// Zero staging: stage1 reads g_s2 directly, stage2 stores magnitudes directly.
__global__ __launch_bounds__(256) void k_invrow(float* __restrict__ out) {
    __shared__ float sre[SMF], sim[SMF];
    const int b = blockIdx.y;
    const int h0 = blockIdx.x * 16;
    const int tid = threadIdx.x;
    const int w = tid >> 5, lane = tid & 31;
    const int t = lane & 15, h = lane >> 4;

    float* re = sre + 482 * w + 240 * h;
    float* im = sim + 482 * w + 240 * h;

    const float2* gsrc = g_s2 + ((size_t)b * 240 + h0 + 2 * w + h) * 240;
    stage1_g<1>(gsrc, re, im, t);

    float* ob = out + ((size_t)b * 240 + h0 + 2 * w + h) * 240;
    stage2_mag_g(re, im, t, ob);
}

extern "C" void kernel_launch(void* const* d_in, const int* in_sizes, int n_in,
                              void* d_out, int out_size) {
    const float* T2_Gen    = (const float*)d_in[0];  // [B,1,240,240] f32
    const float* underT2_K = (const float*)d_in[1];  // [B,2,240,240] f32
    const float* A         = (const float*)d_in[2];  // [240,240] f32
    float* out = (float*)d_out;

    int B = in_sizes[0] / NPIX;   // 256
    dim3 grid(15, B);

    init_tw_kernel<<<1, 256>>>();
    k_rowfft<<<grid, 256>>>(T2_Gen);
    k_colfft<<<grid, 256>>>(underT2_K, A);
    k_invrow<<<grid, 256>>>(out);
}